// round 7
// baseline (speedup 1.0000x reference)
#include <cuda_runtime.h>
#include <cuda_bf16.h>

#define NRAYS 4096
#define NTETS 3072
#define NFACE 12288
#define MAXS  128

// ---------------- scratch (device globals; no allocations) ------------------
__device__ float4 g_btri[NFACE * 3];            // boundary tri: p0,e1,e2; fid in [0].w
__device__ int    g_nb;                          // boundary tri count
__device__ unsigned long long g_key[NRAYS];      // packed (t_bits<<32 | face_idx)

struct F3 { float x, y, z; };
__device__ __forceinline__ F3 mkf3(float x, float y, float z) { F3 r; r.x = x; r.y = y; r.z = z; return r; }
__device__ __forceinline__ F3 sub3(F3 a, F3 b) { return mkf3(a.x - b.x, a.y - b.y, a.z - b.z); }
__device__ __forceinline__ F3 cross3(F3 a, F3 b) {
    return mkf3(a.y * b.z - a.z * b.y,
                a.z * b.x - a.x * b.z,
                a.x * b.y - a.y * b.x);
}
__device__ __forceinline__ float dot3(F3 a, F3 b) { return a.x * b.x + a.y * b.y + a.z * b.z; }
__device__ __forceinline__ F3 ld3(const float* p) { return mkf3(p[0], p[1], p[2]); }

// ---------------- kernel 0: reset boundary counter ---------------------------
__global__ void k_reset() { g_nb = 0; }

// ---------------- kernel 1: compact boundary triangles (grid-wide) -----------
// topo flattened (NTETS*4) is indexed exactly by face id; boundary <=> topo<0.
// Slot order is non-deterministic but the isect min-reduction is order-
// independent ((t, fid) tie-break), so results are deterministic.
__global__ void k_prep(const float* __restrict__ verts,
                       const int* __restrict__ faces,
                       const int* __restrict__ topo) {
    int fid = blockIdx.x * blockDim.x + threadIdx.x;
    if (fid >= NFACE) return;
    if (topo[fid] >= 0) return;                 // interior face: cannot be first hit
    int slot = atomicAdd(&g_nb, 1);
    int v0 = faces[3 * fid + 0];
    int v1 = faces[3 * fid + 1];
    int v2 = faces[3 * fid + 2];
    F3 p0 = ld3(verts + 3 * v0);
    F3 p1 = ld3(verts + 3 * v1);
    F3 p2 = ld3(verts + 3 * v2);
    g_btri[3 * slot + 0] = make_float4(p0.x, p0.y, p0.z, __int_as_float(fid));
    g_btri[3 * slot + 1] = make_float4(p1.x - p0.x, p1.y - p0.y, p1.z - p0.z, 0.0f);
    g_btri[3 * slot + 2] = make_float4(p2.x - p0.x, p2.y - p0.y, p2.z - p0.z, 0.0f);
}

// ---------------- kernel 2: intersect, block-reduced -------------------------
// Block = 512 threads = 32 rays x 16 tri-slices; shared atomicMin on packed
// (t_bits<<32 | fid) reproduces first-occurrence argmin; one coalesced g_key
// write per block.
__global__ void __launch_bounds__(512) k_isect(const float* __restrict__ ro,
                                               const float* __restrict__ rd) {
    __shared__ unsigned long long skey[32];
    int tid  = threadIdx.x;
    int lane = tid & 31;
    int wid  = tid >> 5;                 // 0..15 = tri-slice
    int ray  = blockIdx.x * 32 + lane;

    if (tid < 32)
        skey[tid] = ((unsigned long long)__float_as_uint(1e10f) << 32); // (1e10, 0)
    __syncthreads();

    F3 o = ld3(ro + 3 * ray);
    F3 d = ld3(rd + 3 * ray);
    int nb = g_nb;

    float tmin = 1e10f;
    int   fmin = 0x7fffffff;
    for (int s = wid; s < nb; s += 16) {
        float4 q0 = g_btri[3 * s + 0];
        float4 q1 = g_btri[3 * s + 1];
        float4 q2 = g_btri[3 * s + 2];
        F3 p0 = mkf3(q0.x, q0.y, q0.z);
        F3 e1 = mkf3(q1.x, q1.y, q1.z);
        F3 e2 = mkf3(q2.x, q2.y, q2.z);
        int fid = __float_as_int(q0.w);

        F3 h = cross3(d, e2);
        float a = dot3(e1, h);
        bool anz = fabsf(a) > 1e-9f;
        float f = 1.0f / (anz ? a : 1e-9f);
        F3 s3 = sub3(o, p0);
        float u = f * dot3(s3, h);
        F3 q = cross3(s3, e1);
        float v = f * dot3(d, q);
        float tt = f * dot3(e2, q);
        bool ok = anz && (u >= 0.0f) && (u <= 1.0f) && (v >= 0.0f) &&
                  (u + v <= 1.0f) && (tt > 1e-6f);
        if (ok && (tt < tmin || (tt == tmin && fid < fmin))) { tmin = tt; fmin = fid; }
    }
    if (tmin < 1e10f) {
        unsigned long long key =
            ((unsigned long long)__float_as_uint(tmin) << 32) | (unsigned)fmin;
        atomicMin(&skey[lane], key);
    }
    __syncthreads();
    if (tid < 32) g_key[ray] = skey[tid];
}

// ---------------- kernel 3: march, smem-staged coalesced stores --------------
// 128 blocks x 32 threads; thread = ray (R3's exact step arithmetic).
// Outputs for 8 consecutive steps are staged in padded shared arrays, then
// warp-flushed with lanes remapped to cover 8 consecutive k per ray group:
// ~13x fewer L1 store wavefronts than direct 512B-stride stores, zero idle
// threads, no block-level syncs.
__global__ void __launch_bounds__(32) k_march(const float* __restrict__ verts,
                                              const float* __restrict__ ro,
                                              const float* __restrict__ rd,
                                              const int* __restrict__ tetras,
                                              const int* __restrict__ topo,
                                              float* __restrict__ out) {
    __shared__ float s_ray[32][9], s_tet[32][9];
    __shared__ float s_b0[32][9], s_b1[32][9], s_b2[32][9], s_b3[32][9];
    __shared__ float s_px[32][9], s_py[32][9], s_pz[32][9];

    int lane = threadIdx.x;
    int ray  = blockIdx.x * 32 + lane;

    unsigned long long key = g_key[ray];
    float tmin = __uint_as_float((unsigned)(key >> 32));
    int   fidx = (int)(key & 0xffffffffu);

    bool  hit = tmin < 5.0f;
    float t0  = hit ? tmin : 0.0f;
    F3 o = ld3(ro + 3 * ray);
    F3 d = ld3(rd + 3 * ray);
    F3 hp = mkf3(o.x + t0 * d.x, o.y + t0 * d.y, o.z + t0 * d.z);
    int  tet   = hit ? (fidx >> 2) : 0;
    bool alive = hit;

    float* o_ray = out;
    float* o_tet = out + (size_t)NRAYS * MAXS;
    float* o_bar = out + (size_t)2 * NRAYS * MAXS;
    float* o_ts  = out + (size_t)6 * NRAYS * MAXS;
    float* o_te  = o_ts + NRAYS;
    float* o_pos = o_te + NRAYS;

    o_ts[ray] = t0;
    o_te[ray] = hit ? (t0 + 0.05f) : 0.0f;

    const float STEPF = (float)(0.05 / 128.0);

    // register-cached tet data (identical computation to R3)
    F3 ca, ce1, ce2, ce3, cc23;
    float cinv = 0.0f;
    if (alive) {
        int4 tv = ((const int4*)tetras)[tet];
        ca  = ld3(verts + 3 * tv.x);
        F3 b  = ld3(verts + 3 * tv.y);
        F3 c  = ld3(verts + 3 * tv.z);
        F3 dd = ld3(verts + 3 * tv.w);
        ce1 = sub3(b, ca);
        ce2 = sub3(c, ca);
        ce3 = sub3(dd, ca);
        cc23 = cross3(ce2, ce3);
        float det = dot3(ce1, cc23);
        cinv = 1.0f / det;
    }

    for (int chunk = 0; chunk < MAXS / 8; ++chunk) {
        // -------- compute 8 steps, stage in smem (R3 arithmetic verbatim) ----
        for (int kk = 0; kk < 8; ++kk) {
            int k = chunk * 8 + kk;
            float w0 = 0.f, w1 = 0.f, w2 = 0.f, w3 = 0.f;
            F3 p = mkf3(0.f, 0.f, 0.f);
            bool valid = false;

            if (alive) {
                float tk = (float)k * STEPF + 1e-4f;
                p = mkf3(hp.x + tk * d.x, hp.y + tk * d.y, hp.z + tk * d.z);

                bool inside = false;
                bool moved_last = false;
                for (int it = 0; it < 3; ++it) {
                    F3 r = sub3(p, ca);
                    w1 = dot3(r, cc23) * cinv;
                    F3 cr3 = cross3(r, ce3);
                    w2 = dot3(ce1, cr3) * cinv;
                    F3 c2r = cross3(ce2, r);
                    w3 = dot3(ce1, c2r) * cinv;
                    w0 = 1.0f - (w1 + w2 + w3);
                    inside = (w0 >= -1e-6f) && (w1 >= -1e-6f) &&
                             (w2 >= -1e-6f) && (w3 >= -1e-6f);
                    moved_last = false;
                    if (inside) break;
                    int am = 0; float mv = w0;
                    if (w1 < mv) { mv = w1; am = 1; }
                    if (w2 < mv) { mv = w2; am = 2; }
                    if (w3 < mv) { mv = w3; am = 3; }
                    int nb = topo[4 * tet + (3 - am)];
                    if (nb >= 0) {
                        tet = nb;
                        int4 tv = ((const int4*)tetras)[tet];
                        ca  = ld3(verts + 3 * tv.x);
                        F3 b  = ld3(verts + 3 * tv.y);
                        F3 c  = ld3(verts + 3 * tv.z);
                        F3 dd = ld3(verts + 3 * tv.w);
                        ce1 = sub3(b, ca);
                        ce2 = sub3(c, ca);
                        ce3 = sub3(dd, ca);
                        cc23 = cross3(ce2, ce3);
                        float det = dot3(ce1, cc23);
                        cinv = 1.0f / det;
                        moved_last = true;
                    } else { alive = false; break; }
                }
                if (alive && !inside && moved_last) {
                    F3 r = sub3(p, ca);
                    w1 = dot3(r, cc23) * cinv;
                    F3 cr3 = cross3(r, ce3);
                    w2 = dot3(ce1, cr3) * cinv;
                    F3 c2r = cross3(ce2, r);
                    w3 = dot3(ce1, c2r) * cinv;
                    w0 = 1.0f - (w1 + w2 + w3);
                    inside = (w0 >= -1e-6f) && (w1 >= -1e-6f) &&
                             (w2 >= -1e-6f) && (w3 >= -1e-6f);
                }
                valid = alive && inside;
            }

            if (valid) {
                s_ray[lane][kk] = (float)ray;
                s_tet[lane][kk] = (float)tet;
                s_b0[lane][kk] = w0; s_b1[lane][kk] = w1;
                s_b2[lane][kk] = w2; s_b3[lane][kk] = w3;
                s_px[lane][kk] = p.x; s_py[lane][kk] = p.y; s_pz[lane][kk] = p.z;
            } else {
                s_ray[lane][kk] = -1.0f;
                s_tet[lane][kk] = -1.0f;
                s_b0[lane][kk] = 0.f; s_b1[lane][kk] = 0.f;
                s_b2[lane][kk] = 0.f; s_b3[lane][kk] = 0.f;
                s_px[lane][kk] = 0.f; s_py[lane][kk] = 0.f; s_pz[lane][kk] = 0.f;
            }
        }
        __syncwarp();

        // -------- coalesced flush: lanes cover (4 rays x 8 consecutive k) ----
        int kbase = chunk * 8;
#pragma unroll
        for (int i = 0; i < 8; ++i) {
            int id = i * 32 + lane;          // 0..255
            int r  = id >> 3;                // staged ray row
            int kk = id & 7;
            int idx = (blockIdx.x * 32 + r) * MAXS + kbase + kk;
            o_ray[idx] = s_ray[r][kk];
            o_tet[idx] = s_tet[r][kk];
            ((float4*)o_bar)[idx] =
                make_float4(s_b0[r][kk], s_b1[r][kk], s_b2[r][kk], s_b3[r][kk]);
            o_pos[3 * idx + 0] = s_px[r][kk];
            o_pos[3 * idx + 1] = s_py[r][kk];
            o_pos[3 * idx + 2] = s_pz[r][kk];
        }
        __syncwarp();
    }
}

// ---------------- launch ------------------------------------------------------
extern "C" void kernel_launch(void* const* d_in, const int* in_sizes, int n_in,
                              void* d_out, int out_size) {
    const float* cage   = (const float*)d_in[0];  // (1, 729, 3) f32
    const float* ro     = (const float*)d_in[1];  // (1, 4096, 3) f32
    const float* rd     = (const float*)d_in[2];  // (1, 4096, 3) f32
    const int*   tetras = (const int*)d_in[3];    // (3072, 4) i32
    const int*   faces  = (const int*)d_in[4];    // (3072, 4, 3) i32
    const int*   topo   = (const int*)d_in[5];    // (3072, 4) i32
    float* out = (float*)d_out;

    k_reset<<<1, 1>>>();
    k_prep<<<(NFACE + 255) / 256, 256>>>(cage, faces, topo);
    k_isect<<<NRAYS / 32, 512>>>(ro, rd);
    k_march<<<NRAYS / 32, 32>>>(cage, ro, rd, tetras, topo, out);
}

// round 8
// speedup vs baseline: 2.0489x; 2.0489x over previous
#include <cuda_runtime.h>
#include <cuda_bf16.h>

#define NRAYS 4096
#define NTETS 3072
#define NFACE 12288
#define MAXS  128

// ---------------- scratch (device globals; no allocations) ------------------
__device__ float4 g_btri[NFACE * 3];            // boundary tri: p0,e1,e2; fid in [0].w
__device__ int    g_nb;                          // boundary tri count
__device__ unsigned long long g_key[NRAYS];      // packed (t_bits<<32 | face_idx)

struct F3 { float x, y, z; };
__device__ __forceinline__ F3 mkf3(float x, float y, float z) { F3 r; r.x = x; r.y = y; r.z = z; return r; }
__device__ __forceinline__ F3 sub3(F3 a, F3 b) { return mkf3(a.x - b.x, a.y - b.y, a.z - b.z); }
__device__ __forceinline__ F3 cross3(F3 a, F3 b) {
    return mkf3(a.y * b.z - a.z * b.y,
                a.z * b.x - a.x * b.z,
                a.x * b.y - a.y * b.x);
}
__device__ __forceinline__ float dot3(F3 a, F3 b) { return a.x * b.x + a.y * b.y + a.z * b.z; }
__device__ __forceinline__ F3 ld3(const float* p) { return mkf3(p[0], p[1], p[2]); }

// ---------------- kernel 0: reset boundary counter ---------------------------
__global__ void k_reset() { g_nb = 0; }

// ---------------- kernel 1: compact boundary triangles (grid-wide) -----------
// topo flattened (NTETS*4) is indexed exactly by face id; boundary <=> topo<0.
__global__ void k_prep(const float* __restrict__ verts,
                       const int* __restrict__ faces,
                       const int* __restrict__ topo) {
    int fid = blockIdx.x * blockDim.x + threadIdx.x;
    if (fid >= NFACE) return;
    if (topo[fid] >= 0) return;                 // interior face: cannot be first hit
    int slot = atomicAdd(&g_nb, 1);
    int v0 = faces[3 * fid + 0];
    int v1 = faces[3 * fid + 1];
    int v2 = faces[3 * fid + 2];
    F3 p0 = ld3(verts + 3 * v0);
    F3 p1 = ld3(verts + 3 * v1);
    F3 p2 = ld3(verts + 3 * v2);
    g_btri[3 * slot + 0] = make_float4(p0.x, p0.y, p0.z, __int_as_float(fid));
    g_btri[3 * slot + 1] = make_float4(p1.x - p0.x, p1.y - p0.y, p1.z - p0.z, 0.0f);
    g_btri[3 * slot + 2] = make_float4(p2.x - p0.x, p2.y - p0.y, p2.z - p0.z, 0.0f);
}

// ---------------- kernel 2: intersect, block-reduced -------------------------
__global__ void __launch_bounds__(512) k_isect(const float* __restrict__ ro,
                                               const float* __restrict__ rd) {
    __shared__ unsigned long long skey[32];
    int tid  = threadIdx.x;
    int lane = tid & 31;
    int wid  = tid >> 5;                 // 0..15 = tri-slice
    int ray  = blockIdx.x * 32 + lane;

    if (tid < 32)
        skey[tid] = ((unsigned long long)__float_as_uint(1e10f) << 32); // (1e10, 0)
    __syncthreads();

    F3 o = ld3(ro + 3 * ray);
    F3 d = ld3(rd + 3 * ray);
    int nb = g_nb;

    float tmin = 1e10f;
    int   fmin = 0x7fffffff;
    for (int s = wid; s < nb; s += 16) {
        float4 q0 = g_btri[3 * s + 0];
        float4 q1 = g_btri[3 * s + 1];
        float4 q2 = g_btri[3 * s + 2];
        F3 p0 = mkf3(q0.x, q0.y, q0.z);
        F3 e1 = mkf3(q1.x, q1.y, q1.z);
        F3 e2 = mkf3(q2.x, q2.y, q2.z);
        int fid = __float_as_int(q0.w);

        F3 h = cross3(d, e2);
        float a = dot3(e1, h);
        bool anz = fabsf(a) > 1e-9f;
        float f = 1.0f / (anz ? a : 1e-9f);
        F3 s3 = sub3(o, p0);
        float u = f * dot3(s3, h);
        F3 q = cross3(s3, e1);
        float v = f * dot3(d, q);
        float tt = f * dot3(e2, q);
        bool ok = anz && (u >= 0.0f) && (u <= 1.0f) && (v >= 0.0f) &&
                  (u + v <= 1.0f) && (tt > 1e-6f);
        if (ok && (tt < tmin || (tt == tmin && fid < fmin))) { tmin = tt; fmin = fid; }
    }
    if (tmin < 1e10f) {
        unsigned long long key =
            ((unsigned long long)__float_as_uint(tmin) << 32) | (unsigned)fmin;
        atomicMin(&skey[lane], key);
    }
    __syncthreads();
    if (tid < 32) g_key[ray] = skey[tid];
}

// ---------------- kernel 3: march, warp-per-ray speculative stepping ---------
// One warp per ray. Per batch: 32 lanes evaluate bary(p_{k+lane}, T) against
// the uniform cached tet T; ballot finds the first non-inside step; earlier
// lanes emit directly (reference emits exactly bary(p,T) there); all lanes
// redundantly run the verbatim R3 walk for the failing step, then continue.
// All per-ray state is warp-uniform -> no shuffles, no divergence.
__global__ void __launch_bounds__(256) k_march(const float* __restrict__ verts,
                                               const float* __restrict__ ro,
                                               const float* __restrict__ rd,
                                               const int* __restrict__ tetras,
                                               const int* __restrict__ topo,
                                               float* __restrict__ out) {
    int lane = threadIdx.x & 31;
    int ray  = blockIdx.x * 8 + (threadIdx.x >> 5);

    unsigned long long key = g_key[ray];
    float tmin = __uint_as_float((unsigned)(key >> 32));
    int   fidx = (int)(key & 0xffffffffu);

    bool  hit = tmin < 5.0f;
    float t0  = hit ? tmin : 0.0f;
    F3 o = ld3(ro + 3 * ray);
    F3 d = ld3(rd + 3 * ray);
    F3 hp = mkf3(o.x + t0 * d.x, o.y + t0 * d.y, o.z + t0 * d.z);
    int  tet   = hit ? (fidx >> 2) : 0;
    bool alive = hit;

    float* o_ray = out;
    float* o_tet = out + (size_t)NRAYS * MAXS;
    float* o_bar = out + (size_t)2 * NRAYS * MAXS;
    float* o_ts  = out + (size_t)6 * NRAYS * MAXS;
    float* o_te  = o_ts + NRAYS;
    float* o_pos = o_te + NRAYS;

    if (lane == 0) {
        o_ts[ray] = t0;
        o_te[ray] = hit ? (t0 + 0.05f) : 0.0f;
    }

    const float STEPF = (float)(0.05 / 128.0);

    // warp-uniform register cache of the current tet (R3's exact preamble)
    F3 ca, ce1, ce2, ce3, cc23;
    float cinv = 0.0f;
    if (alive) {
        int4 tv = ((const int4*)tetras)[tet];
        ca  = ld3(verts + 3 * tv.x);
        F3 b  = ld3(verts + 3 * tv.y);
        F3 c  = ld3(verts + 3 * tv.z);
        F3 dd = ld3(verts + 3 * tv.w);
        ce1 = sub3(b, ca);
        ce2 = sub3(c, ca);
        ce3 = sub3(dd, ca);
        cc23 = cross3(ce2, ce3);
        float det = dot3(ce1, cc23);
        cinv = 1.0f / det;
    }

    int k = 0;
    while (k < MAXS) {
        if (!alive) {
            // fill the remaining steps invalid, coalesced across lanes
            for (int kk = k + lane; kk < MAXS; kk += 32) {
                int idx = ray * MAXS + kk;
                o_ray[idx] = -1.0f;
                o_tet[idx] = -1.0f;
                ((float4*)o_bar)[idx] = make_float4(0.f, 0.f, 0.f, 0.f);
                o_pos[3 * idx + 0] = 0.0f;
                o_pos[3 * idx + 1] = 0.0f;
                o_pos[3 * idx + 2] = 0.0f;
            }
            break;
        }

        int count = MAXS - k;
        if (count > 32) count = 32;

        // ---- speculative parallel bary for steps k..k+count-1 (tet T) ------
        float w0 = 0.f, w1 = 0.f, w2 = 0.f, w3 = 0.f;
        F3 p = mkf3(0.f, 0.f, 0.f);
        bool inside = false;
        if (lane < count) {
            float tk = (float)(k + lane) * STEPF + 1e-4f;
            p = mkf3(hp.x + tk * d.x, hp.y + tk * d.y, hp.z + tk * d.z);
            F3 r = sub3(p, ca);
            w1 = dot3(r, cc23) * cinv;
            F3 cr3 = cross3(r, ce3);
            w2 = dot3(ce1, cr3) * cinv;
            F3 c2r = cross3(ce2, r);
            w3 = dot3(ce1, c2r) * cinv;
            w0 = 1.0f - (w1 + w2 + w3);
            inside = (w0 >= -1e-6f) && (w1 >= -1e-6f) &&
                     (w2 >= -1e-6f) && (w3 >= -1e-6f);
        }
        unsigned bal = __ballot_sync(0xffffffffu, (lane < count) && !inside);
        int n_ok = (bal == 0u) ? count : (__ffs(bal) - 1);

        // ---- emit the n_ok proven-inside steps (lane-consecutive stores) ---
        if (lane < n_ok) {
            int idx = ray * MAXS + k + lane;
            o_ray[idx] = (float)ray;
            o_tet[idx] = (float)tet;
            ((float4*)o_bar)[idx] = make_float4(w0, w1, w2, w3);
            o_pos[3 * idx + 0] = p.x;
            o_pos[3 * idx + 1] = p.y;
            o_pos[3 * idx + 2] = p.z;
        }
        k += n_ok;
        if (bal == 0u) continue;

        // ---- failing step k: all lanes redundantly run the R3 walk ---------
        {
            float tk = (float)k * STEPF + 1e-4f;
            F3 pw = mkf3(hp.x + tk * d.x, hp.y + tk * d.y, hp.z + tk * d.z);
            float v0 = 0.f, v1 = 0.f, v2 = 0.f, v3 = 0.f;
            bool ins = false;
            bool moved_last = false;
            for (int it = 0; it < 3; ++it) {
                F3 r = sub3(pw, ca);
                v1 = dot3(r, cc23) * cinv;
                F3 cr3 = cross3(r, ce3);
                v2 = dot3(ce1, cr3) * cinv;
                F3 c2r = cross3(ce2, r);
                v3 = dot3(ce1, c2r) * cinv;
                v0 = 1.0f - (v1 + v2 + v3);
                ins = (v0 >= -1e-6f) && (v1 >= -1e-6f) &&
                      (v2 >= -1e-6f) && (v3 >= -1e-6f);
                moved_last = false;
                if (ins) break;
                int am = 0; float mv = v0;
                if (v1 < mv) { mv = v1; am = 1; }
                if (v2 < mv) { mv = v2; am = 2; }
                if (v3 < mv) { mv = v3; am = 3; }
                int nb = topo[4 * tet + (3 - am)];
                if (nb >= 0) {
                    tet = nb;
                    int4 tv = ((const int4*)tetras)[tet];
                    ca  = ld3(verts + 3 * tv.x);
                    F3 b  = ld3(verts + 3 * tv.y);
                    F3 c  = ld3(verts + 3 * tv.z);
                    F3 dd = ld3(verts + 3 * tv.w);
                    ce1 = sub3(b, ca);
                    ce2 = sub3(c, ca);
                    ce3 = sub3(dd, ca);
                    cc23 = cross3(ce2, ce3);
                    float det = dot3(ce1, cc23);
                    cinv = 1.0f / det;
                    moved_last = true;
                } else { alive = false; break; }
            }
            if (alive && !ins && moved_last) {
                F3 r = sub3(pw, ca);
                v1 = dot3(r, cc23) * cinv;
                F3 cr3 = cross3(r, ce3);
                v2 = dot3(ce1, cr3) * cinv;
                F3 c2r = cross3(ce2, r);
                v3 = dot3(ce1, c2r) * cinv;
                v0 = 1.0f - (v1 + v2 + v3);
                ins = (v0 >= -1e-6f) && (v1 >= -1e-6f) &&
                      (v2 >= -1e-6f) && (v3 >= -1e-6f);
            }
            bool valid = alive && ins;

            if (lane == 0) {
                int idx = ray * MAXS + k;
                if (valid) {
                    o_ray[idx] = (float)ray;
                    o_tet[idx] = (float)tet;
                    ((float4*)o_bar)[idx] = make_float4(v0, v1, v2, v3);
                    o_pos[3 * idx + 0] = pw.x;
                    o_pos[3 * idx + 1] = pw.y;
                    o_pos[3 * idx + 2] = pw.z;
                } else {
                    o_ray[idx] = -1.0f;
                    o_tet[idx] = -1.0f;
                    ((float4*)o_bar)[idx] = make_float4(0.f, 0.f, 0.f, 0.f);
                    o_pos[3 * idx + 0] = 0.0f;
                    o_pos[3 * idx + 1] = 0.0f;
                    o_pos[3 * idx + 2] = 0.0f;
                }
            }
            k += 1;
        }
    }
}

// ---------------- launch ------------------------------------------------------
extern "C" void kernel_launch(void* const* d_in, const int* in_sizes, int n_in,
                              void* d_out, int out_size) {
    const float* cage   = (const float*)d_in[0];  // (1, 729, 3) f32
    const float* ro     = (const float*)d_in[1];  // (1, 4096, 3) f32
    const float* rd     = (const float*)d_in[2];  // (1, 4096, 3) f32
    const int*   tetras = (const int*)d_in[3];    // (3072, 4) i32
    const int*   faces  = (const int*)d_in[4];    // (3072, 4, 3) i32
    const int*   topo   = (const int*)d_in[5];    // (3072, 4) i32
    float* out = (float*)d_out;

    k_reset<<<1, 1>>>();
    k_prep<<<(NFACE + 255) / 256, 256>>>(cage, faces, topo);
    k_isect<<<NRAYS / 32, 512>>>(ro, rd);
    k_march<<<NRAYS / 8, 256>>>(cage, ro, rd, tetras, topo, out);
}

// round 9
// speedup vs baseline: 2.7232x; 1.3291x over previous
#include <cuda_runtime.h>
#include <cuda_bf16.h>

#define NRAYS 4096
#define NTETS 3072
#define NFACE 12288
#define MAXS  128

// ---------------- scratch (device globals; no allocations) ------------------
__device__ float4 g_btri[NFACE * 3];            // boundary tri: p0,e1,e2; fid in [0].w
__device__ int    g_nb;                          // boundary tri count

struct F3 { float x, y, z; };
__device__ __forceinline__ F3 mkf3(float x, float y, float z) { F3 r; r.x = x; r.y = y; r.z = z; return r; }
__device__ __forceinline__ F3 sub3(F3 a, F3 b) { return mkf3(a.x - b.x, a.y - b.y, a.z - b.z); }
__device__ __forceinline__ F3 cross3(F3 a, F3 b) {
    return mkf3(a.y * b.z - a.z * b.y,
                a.z * b.x - a.x * b.z,
                a.x * b.y - a.y * b.x);
}
__device__ __forceinline__ float dot3(F3 a, F3 b) { return a.x * b.x + a.y * b.y + a.z * b.z; }
__device__ __forceinline__ F3 ld3(const float* p) { return mkf3(p[0], p[1], p[2]); }

// ---------------- kernel 0: reset boundary counter ---------------------------
__global__ void k_reset() { g_nb = 0; }

// ---------------- kernel 1: compact boundary triangles (grid-wide) -----------
// topo flattened (NTETS*4) is indexed exactly by face id; boundary <=> topo<0.
// Slot order is non-deterministic but the isect min-reduction is order-
// independent ((t, fid) tie-break), so results are deterministic.
__global__ void k_prep(const float* __restrict__ verts,
                       const int* __restrict__ faces,
                       const int* __restrict__ topo) {
    int fid = blockIdx.x * blockDim.x + threadIdx.x;
    if (fid >= NFACE) return;
    if (topo[fid] >= 0) return;                 // interior face: cannot be first hit
    int slot = atomicAdd(&g_nb, 1);
    int v0 = faces[3 * fid + 0];
    int v1 = faces[3 * fid + 1];
    int v2 = faces[3 * fid + 2];
    F3 p0 = ld3(verts + 3 * v0);
    F3 p1 = ld3(verts + 3 * v1);
    F3 p2 = ld3(verts + 3 * v2);
    g_btri[3 * slot + 0] = make_float4(p0.x, p0.y, p0.z, __int_as_float(fid));
    g_btri[3 * slot + 1] = make_float4(p1.x - p0.x, p1.y - p0.y, p1.z - p0.z, 0.0f);
    g_btri[3 * slot + 2] = make_float4(p2.x - p0.x, p2.y - p0.y, p2.z - p0.z, 0.0f);
}

// ---------------- kernel 2: fused intersect + march ---------------------------
// 128 blocks x 1024 threads (32 warps).
// Phase 1 (isect): 32 rays x 32 tri-slices; thread (lane=ray, wid=slice) runs
//   Moller-Trumbore over its slice; shared atomicMin on packed (t_bits<<32|fid)
//   reproduces first-occurrence argmin.
// Phase 2 (march): warp w marches ray w with R8's warp-per-ray speculative
//   stepping: 32 lanes evaluate bary for 32 consecutive steps against the
//   uniform cached tet; ballot finds the first non-inside step; earlier lanes
//   emit directly; all lanes redundantly run the verbatim R3 walk for the
//   failing step; repeat. All emitted arithmetic identical to R3/R8.
__global__ void __launch_bounds__(1024) k_fused(const float* __restrict__ verts,
                                                const float* __restrict__ ro,
                                                const float* __restrict__ rd,
                                                const int* __restrict__ tetras,
                                                const int* __restrict__ topo,
                                                float* __restrict__ out) {
    __shared__ unsigned long long skey[32];

    int tid  = threadIdx.x;
    int lane = tid & 31;
    int wid  = tid >> 5;                 // 0..31

    if (tid < 32)
        skey[tid] = ((unsigned long long)__float_as_uint(1e10f) << 32); // (1e10, 0)
    __syncthreads();

    // ---------------- phase 1: intersect (ray = lane, slice = wid) -----------
    {
        int iray = blockIdx.x * 32 + lane;
        F3 o = ld3(ro + 3 * iray);
        F3 d = ld3(rd + 3 * iray);
        int nb = g_nb;

        float tmin = 1e10f;
        int   fmin = 0x7fffffff;
        for (int s = wid; s < nb; s += 32) {
            float4 q0 = g_btri[3 * s + 0];
            float4 q1 = g_btri[3 * s + 1];
            float4 q2 = g_btri[3 * s + 2];
            F3 p0 = mkf3(q0.x, q0.y, q0.z);
            F3 e1 = mkf3(q1.x, q1.y, q1.z);
            F3 e2 = mkf3(q2.x, q2.y, q2.z);
            int fid = __float_as_int(q0.w);

            F3 h = cross3(d, e2);
            float a = dot3(e1, h);
            bool anz = fabsf(a) > 1e-9f;
            float f = 1.0f / (anz ? a : 1e-9f);
            F3 s3 = sub3(o, p0);
            float u = f * dot3(s3, h);
            F3 q = cross3(s3, e1);
            float v = f * dot3(d, q);
            float tt = f * dot3(e2, q);
            bool ok = anz && (u >= 0.0f) && (u <= 1.0f) && (v >= 0.0f) &&
                      (u + v <= 1.0f) && (tt > 1e-6f);
            if (ok && (tt < tmin || (tt == tmin && fid < fmin))) { tmin = tt; fmin = fid; }
        }
        if (tmin < 1e10f) {
            unsigned long long key =
                ((unsigned long long)__float_as_uint(tmin) << 32) | (unsigned)fmin;
            atomicMin(&skey[lane], key);
        }
    }
    __syncthreads();

    // ---------------- phase 2: march (warp = ray) -----------------------------
    int ray = blockIdx.x * 32 + wid;

    unsigned long long key = skey[wid];
    float tmin = __uint_as_float((unsigned)(key >> 32));
    int   fidx = (int)(key & 0xffffffffu);

    bool  hit = tmin < 5.0f;
    float t0  = hit ? tmin : 0.0f;
    F3 o = ld3(ro + 3 * ray);
    F3 d = ld3(rd + 3 * ray);
    F3 hp = mkf3(o.x + t0 * d.x, o.y + t0 * d.y, o.z + t0 * d.z);
    int  tet   = hit ? (fidx >> 2) : 0;
    bool alive = hit;

    float* o_ray = out;
    float* o_tet = out + (size_t)NRAYS * MAXS;
    float* o_bar = out + (size_t)2 * NRAYS * MAXS;
    float* o_ts  = out + (size_t)6 * NRAYS * MAXS;
    float* o_te  = o_ts + NRAYS;
    float* o_pos = o_te + NRAYS;

    if (lane == 0) {
        o_ts[ray] = t0;
        o_te[ray] = hit ? (t0 + 0.05f) : 0.0f;
    }

    const float STEPF = (float)(0.05 / 128.0);

    // warp-uniform register cache of the current tet (R3's exact preamble)
    F3 ca, ce1, ce2, ce3, cc23;
    float cinv = 0.0f;
    if (alive) {
        int4 tv = ((const int4*)tetras)[tet];
        ca  = ld3(verts + 3 * tv.x);
        F3 b  = ld3(verts + 3 * tv.y);
        F3 c  = ld3(verts + 3 * tv.z);
        F3 dd = ld3(verts + 3 * tv.w);
        ce1 = sub3(b, ca);
        ce2 = sub3(c, ca);
        ce3 = sub3(dd, ca);
        cc23 = cross3(ce2, ce3);
        float det = dot3(ce1, cc23);
        cinv = 1.0f / det;
    }

    int k = 0;
    while (k < MAXS) {
        if (!alive) {
            for (int kk = k + lane; kk < MAXS; kk += 32) {
                int idx = ray * MAXS + kk;
                o_ray[idx] = -1.0f;
                o_tet[idx] = -1.0f;
                ((float4*)o_bar)[idx] = make_float4(0.f, 0.f, 0.f, 0.f);
                o_pos[3 * idx + 0] = 0.0f;
                o_pos[3 * idx + 1] = 0.0f;
                o_pos[3 * idx + 2] = 0.0f;
            }
            break;
        }

        int count = MAXS - k;
        if (count > 32) count = 32;

        // ---- speculative parallel bary for steps k..k+count-1 (tet T) ------
        float w0 = 0.f, w1 = 0.f, w2 = 0.f, w3 = 0.f;
        F3 p = mkf3(0.f, 0.f, 0.f);
        bool inside = false;
        if (lane < count) {
            float tk = (float)(k + lane) * STEPF + 1e-4f;
            p = mkf3(hp.x + tk * d.x, hp.y + tk * d.y, hp.z + tk * d.z);
            F3 r = sub3(p, ca);
            w1 = dot3(r, cc23) * cinv;
            F3 cr3 = cross3(r, ce3);
            w2 = dot3(ce1, cr3) * cinv;
            F3 c2r = cross3(ce2, r);
            w3 = dot3(ce1, c2r) * cinv;
            w0 = 1.0f - (w1 + w2 + w3);
            inside = (w0 >= -1e-6f) && (w1 >= -1e-6f) &&
                     (w2 >= -1e-6f) && (w3 >= -1e-6f);
        }
        unsigned bal = __ballot_sync(0xffffffffu, (lane < count) && !inside);
        int n_ok = (bal == 0u) ? count : (__ffs(bal) - 1);

        // ---- emit the n_ok proven-inside steps (lane-consecutive stores) ---
        if (lane < n_ok) {
            int idx = ray * MAXS + k + lane;
            o_ray[idx] = (float)ray;
            o_tet[idx] = (float)tet;
            ((float4*)o_bar)[idx] = make_float4(w0, w1, w2, w3);
            o_pos[3 * idx + 0] = p.x;
            o_pos[3 * idx + 1] = p.y;
            o_pos[3 * idx + 2] = p.z;
        }
        k += n_ok;
        if (bal == 0u) continue;

        // ---- failing step k: all lanes redundantly run the R3 walk ---------
        {
            float tk = (float)k * STEPF + 1e-4f;
            F3 pw = mkf3(hp.x + tk * d.x, hp.y + tk * d.y, hp.z + tk * d.z);
            float v0 = 0.f, v1 = 0.f, v2 = 0.f, v3 = 0.f;
            bool ins = false;
            bool moved_last = false;
            for (int it = 0; it < 3; ++it) {
                F3 r = sub3(pw, ca);
                v1 = dot3(r, cc23) * cinv;
                F3 cr3 = cross3(r, ce3);
                v2 = dot3(ce1, cr3) * cinv;
                F3 c2r = cross3(ce2, r);
                v3 = dot3(ce1, c2r) * cinv;
                v0 = 1.0f - (v1 + v2 + v3);
                ins = (v0 >= -1e-6f) && (v1 >= -1e-6f) &&
                      (v2 >= -1e-6f) && (v3 >= -1e-6f);
                moved_last = false;
                if (ins) break;
                int am = 0; float mv = v0;
                if (v1 < mv) { mv = v1; am = 1; }
                if (v2 < mv) { mv = v2; am = 2; }
                if (v3 < mv) { mv = v3; am = 3; }
                int nb = topo[4 * tet + (3 - am)];
                if (nb >= 0) {
                    tet = nb;
                    int4 tv = ((const int4*)tetras)[tet];
                    ca  = ld3(verts + 3 * tv.x);
                    F3 b  = ld3(verts + 3 * tv.y);
                    F3 c  = ld3(verts + 3 * tv.z);
                    F3 dd = ld3(verts + 3 * tv.w);
                    ce1 = sub3(b, ca);
                    ce2 = sub3(c, ca);
                    ce3 = sub3(dd, ca);
                    cc23 = cross3(ce2, ce3);
                    float det = dot3(ce1, cc23);
                    cinv = 1.0f / det;
                    moved_last = true;
                } else { alive = false; break; }
            }
            if (alive && !ins && moved_last) {
                F3 r = sub3(pw, ca);
                v1 = dot3(r, cc23) * cinv;
                F3 cr3 = cross3(r, ce3);
                v2 = dot3(ce1, cr3) * cinv;
                F3 c2r = cross3(ce2, r);
                v3 = dot3(ce1, c2r) * cinv;
                v0 = 1.0f - (v1 + v2 + v3);
                ins = (v0 >= -1e-6f) && (v1 >= -1e-6f) &&
                      (v2 >= -1e-6f) && (v3 >= -1e-6f);
            }
            bool valid = alive && ins;

            if (lane == 0) {
                int idx = ray * MAXS + k;
                if (valid) {
                    o_ray[idx] = (float)ray;
                    o_tet[idx] = (float)tet;
                    ((float4*)o_bar)[idx] = make_float4(v0, v1, v2, v3);
                    o_pos[3 * idx + 0] = pw.x;
                    o_pos[3 * idx + 1] = pw.y;
                    o_pos[3 * idx + 2] = pw.z;
                } else {
                    o_ray[idx] = -1.0f;
                    o_tet[idx] = -1.0f;
                    ((float4*)o_bar)[idx] = make_float4(0.f, 0.f, 0.f, 0.f);
                    o_pos[3 * idx + 0] = 0.0f;
                    o_pos[3 * idx + 1] = 0.0f;
                    o_pos[3 * idx + 2] = 0.0f;
                }
            }
            k += 1;
        }
    }
}

// ---------------- launch ------------------------------------------------------
extern "C" void kernel_launch(void* const* d_in, const int* in_sizes, int n_in,
                              void* d_out, int out_size) {
    const float* cage   = (const float*)d_in[0];  // (1, 729, 3) f32
    const float* ro     = (const float*)d_in[1];  // (1, 4096, 3) f32
    const float* rd     = (const float*)d_in[2];  // (1, 4096, 3) f32
    const int*   tetras = (const int*)d_in[3];    // (3072, 4) i32
    const int*   faces  = (const int*)d_in[4];    // (3072, 4, 3) i32
    const int*   topo   = (const int*)d_in[5];    // (3072, 4) i32
    float* out = (float*)d_out;

    k_reset<<<1, 1>>>();
    k_prep<<<(NFACE + 255) / 256, 256>>>(cage, faces, topo);
    k_fused<<<NRAYS / 32, 1024>>>(cage, ro, rd, tetras, topo, out);
}

// round 10
// speedup vs baseline: 2.7267x; 1.0013x over previous
#include <cuda_runtime.h>
#include <cuda_bf16.h>

#define NRAYS 4096
#define NTETS 3072
#define NFACE 12288
#define MAXS  128
#define MAXB  896          // boundary-tri capacity (actual count = 768)

struct F3 { float x, y, z; };
__device__ __forceinline__ F3 mkf3(float x, float y, float z) { F3 r; r.x = x; r.y = y; r.z = z; return r; }
__device__ __forceinline__ F3 sub3(F3 a, F3 b) { return mkf3(a.x - b.x, a.y - b.y, a.z - b.z); }
__device__ __forceinline__ F3 cross3(F3 a, F3 b) {
    return mkf3(a.y * b.z - a.z * b.y,
                a.z * b.x - a.x * b.z,
                a.x * b.y - a.y * b.x);
}
__device__ __forceinline__ float dot3(F3 a, F3 b) { return a.x * b.x + a.y * b.y + a.z * b.z; }
__device__ __forceinline__ F3 ld3(const float* p) { return mkf3(p[0], p[1], p[2]); }

// ---------------- single fused kernel -----------------------------------------
// 128 blocks x 1024 threads (32 warps). No global scratch, no reset kernel:
// Phase 0 (prep, per block): scan topo (flattened NTETS*4 == face ids;
//   boundary <=> topo<0; first hit from outside a watertight mesh is always a
//   boundary face), compact boundary tris (p0,e1,e2; fid in q0.w) into smem
//   via a BLOCK-LOCAL atomic counter. Slot order nondeterministic; irrelevant,
//   the min-reduction below is order-independent via the (t, fid) tie-break.
// Phase 1 (isect): 32 rays x 32 tri-slices over the smem tri list;
//   shared atomicMin on packed (t_bits<<32 | fid) == first-occurrence argmin.
// Phase 2 (march): warp w marches ray w; 32 lanes evaluate bary for 32
//   consecutive steps against the warp-uniform register-cached tet; ballot
//   finds the first non-inside step; earlier lanes emit directly; all lanes
//   redundantly run the verbatim R3 walk for the failing step; repeat.
//   All emitted arithmetic identical to R3/R8/R9.
__global__ void __launch_bounds__(1024) k_all(const float* __restrict__ verts,
                                              const float* __restrict__ ro,
                                              const float* __restrict__ rd,
                                              const int* __restrict__ tetras,
                                              const int* __restrict__ faces,
                                              const int* __restrict__ topo,
                                              float* __restrict__ out) {
    __shared__ float4 s_tri[MAXB * 3];
    __shared__ int s_nb;
    __shared__ unsigned long long skey[32];

    int tid  = threadIdx.x;
    int lane = tid & 31;
    int wid  = tid >> 5;                 // 0..31

    if (tid == 0) s_nb = 0;
    if (tid < 32)
        skey[tid] = ((unsigned long long)__float_as_uint(1e10f) << 32); // (1e10, 0)
    __syncthreads();

    // ---------------- phase 0: per-block boundary-tri compaction -------------
    for (int fid = tid; fid < NFACE; fid += 1024) {
        if (topo[fid] < 0) {
            int slot = atomicAdd(&s_nb, 1);
            if (slot < MAXB) {
                int v0 = faces[3 * fid + 0];
                int v1 = faces[3 * fid + 1];
                int v2 = faces[3 * fid + 2];
                F3 p0 = ld3(verts + 3 * v0);
                F3 p1 = ld3(verts + 3 * v1);
                F3 p2 = ld3(verts + 3 * v2);
                s_tri[3 * slot + 0] = make_float4(p0.x, p0.y, p0.z, __int_as_float(fid));
                s_tri[3 * slot + 1] = make_float4(p1.x - p0.x, p1.y - p0.y, p1.z - p0.z, 0.0f);
                s_tri[3 * slot + 2] = make_float4(p2.x - p0.x, p2.y - p0.y, p2.z - p0.z, 0.0f);
            }
        }
    }
    __syncthreads();

    // ---------------- phase 1: intersect (ray = lane, slice = wid) -----------
    {
        int iray = blockIdx.x * 32 + lane;
        F3 o = ld3(ro + 3 * iray);
        F3 d = ld3(rd + 3 * iray);
        int nb = s_nb;
        if (nb > MAXB) nb = MAXB;

        float tmin = 1e10f;
        int   fmin = 0x7fffffff;
        for (int s = wid; s < nb; s += 32) {
            float4 q0 = s_tri[3 * s + 0];
            float4 q1 = s_tri[3 * s + 1];
            float4 q2 = s_tri[3 * s + 2];
            F3 p0 = mkf3(q0.x, q0.y, q0.z);
            F3 e1 = mkf3(q1.x, q1.y, q1.z);
            F3 e2 = mkf3(q2.x, q2.y, q2.z);
            int fid = __float_as_int(q0.w);

            F3 h = cross3(d, e2);
            float a = dot3(e1, h);
            bool anz = fabsf(a) > 1e-9f;
            float f = 1.0f / (anz ? a : 1e-9f);
            F3 s3 = sub3(o, p0);
            float u = f * dot3(s3, h);
            F3 q = cross3(s3, e1);
            float v = f * dot3(d, q);
            float tt = f * dot3(e2, q);
            bool ok = anz && (u >= 0.0f) && (u <= 1.0f) && (v >= 0.0f) &&
                      (u + v <= 1.0f) && (tt > 1e-6f);
            if (ok && (tt < tmin || (tt == tmin && fid < fmin))) { tmin = tt; fmin = fid; }
        }
        if (tmin < 1e10f) {
            unsigned long long key =
                ((unsigned long long)__float_as_uint(tmin) << 32) | (unsigned)fmin;
            atomicMin(&skey[lane], key);
        }
    }
    __syncthreads();

    // ---------------- phase 2: march (warp = ray) -----------------------------
    int ray = blockIdx.x * 32 + wid;

    unsigned long long key = skey[wid];
    float tmin = __uint_as_float((unsigned)(key >> 32));
    int   fidx = (int)(key & 0xffffffffu);

    bool  hit = tmin < 5.0f;
    float t0  = hit ? tmin : 0.0f;
    F3 o = ld3(ro + 3 * ray);
    F3 d = ld3(rd + 3 * ray);
    F3 hp = mkf3(o.x + t0 * d.x, o.y + t0 * d.y, o.z + t0 * d.z);
    int  tet   = hit ? (fidx >> 2) : 0;
    bool alive = hit;

    float* o_ray = out;
    float* o_tet = out + (size_t)NRAYS * MAXS;
    float* o_bar = out + (size_t)2 * NRAYS * MAXS;
    float* o_ts  = out + (size_t)6 * NRAYS * MAXS;
    float* o_te  = o_ts + NRAYS;
    float* o_pos = o_te + NRAYS;

    if (lane == 0) {
        o_ts[ray] = t0;
        o_te[ray] = hit ? (t0 + 0.05f) : 0.0f;
    }

    const float STEPF = (float)(0.05 / 128.0);

    // warp-uniform register cache of the current tet (R3's exact preamble)
    F3 ca, ce1, ce2, ce3, cc23;
    float cinv = 0.0f;
    if (alive) {
        int4 tv = ((const int4*)tetras)[tet];
        ca  = ld3(verts + 3 * tv.x);
        F3 b  = ld3(verts + 3 * tv.y);
        F3 c  = ld3(verts + 3 * tv.z);
        F3 dd = ld3(verts + 3 * tv.w);
        ce1 = sub3(b, ca);
        ce2 = sub3(c, ca);
        ce3 = sub3(dd, ca);
        cc23 = cross3(ce2, ce3);
        float det = dot3(ce1, cc23);
        cinv = 1.0f / det;
    }

    int k = 0;
    while (k < MAXS) {
        if (!alive) {
            for (int kk = k + lane; kk < MAXS; kk += 32) {
                int idx = ray * MAXS + kk;
                o_ray[idx] = -1.0f;
                o_tet[idx] = -1.0f;
                ((float4*)o_bar)[idx] = make_float4(0.f, 0.f, 0.f, 0.f);
                o_pos[3 * idx + 0] = 0.0f;
                o_pos[3 * idx + 1] = 0.0f;
                o_pos[3 * idx + 2] = 0.0f;
            }
            break;
        }

        int count = MAXS - k;
        if (count > 32) count = 32;

        // ---- speculative parallel bary for steps k..k+count-1 (tet T) ------
        float w0 = 0.f, w1 = 0.f, w2 = 0.f, w3 = 0.f;
        F3 p = mkf3(0.f, 0.f, 0.f);
        bool inside = false;
        if (lane < count) {
            float tk = (float)(k + lane) * STEPF + 1e-4f;
            p = mkf3(hp.x + tk * d.x, hp.y + tk * d.y, hp.z + tk * d.z);
            F3 r = sub3(p, ca);
            w1 = dot3(r, cc23) * cinv;
            F3 cr3 = cross3(r, ce3);
            w2 = dot3(ce1, cr3) * cinv;
            F3 c2r = cross3(ce2, r);
            w3 = dot3(ce1, c2r) * cinv;
            w0 = 1.0f - (w1 + w2 + w3);
            inside = (w0 >= -1e-6f) && (w1 >= -1e-6f) &&
                     (w2 >= -1e-6f) && (w3 >= -1e-6f);
        }
        unsigned bal = __ballot_sync(0xffffffffu, (lane < count) && !inside);
        int n_ok = (bal == 0u) ? count : (__ffs(bal) - 1);

        // ---- emit the n_ok proven-inside steps (lane-consecutive stores) ---
        if (lane < n_ok) {
            int idx = ray * MAXS + k + lane;
            o_ray[idx] = (float)ray;
            o_tet[idx] = (float)tet;
            ((float4*)o_bar)[idx] = make_float4(w0, w1, w2, w3);
            o_pos[3 * idx + 0] = p.x;
            o_pos[3 * idx + 1] = p.y;
            o_pos[3 * idx + 2] = p.z;
        }
        k += n_ok;
        if (bal == 0u) continue;

        // ---- failing step k: all lanes redundantly run the R3 walk ---------
        {
            float tk = (float)k * STEPF + 1e-4f;
            F3 pw = mkf3(hp.x + tk * d.x, hp.y + tk * d.y, hp.z + tk * d.z);
            float v0 = 0.f, v1 = 0.f, v2 = 0.f, v3 = 0.f;
            bool ins = false;
            bool moved_last = false;
            for (int it = 0; it < 3; ++it) {
                F3 r = sub3(pw, ca);
                v1 = dot3(r, cc23) * cinv;
                F3 cr3 = cross3(r, ce3);
                v2 = dot3(ce1, cr3) * cinv;
                F3 c2r = cross3(ce2, r);
                v3 = dot3(ce1, c2r) * cinv;
                v0 = 1.0f - (v1 + v2 + v3);
                ins = (v0 >= -1e-6f) && (v1 >= -1e-6f) &&
                      (v2 >= -1e-6f) && (v3 >= -1e-6f);
                moved_last = false;
                if (ins) break;
                int am = 0; float mv = v0;
                if (v1 < mv) { mv = v1; am = 1; }
                if (v2 < mv) { mv = v2; am = 2; }
                if (v3 < mv) { mv = v3; am = 3; }
                int nb = topo[4 * tet + (3 - am)];
                if (nb >= 0) {
                    tet = nb;
                    int4 tv = ((const int4*)tetras)[tet];
                    ca  = ld3(verts + 3 * tv.x);
                    F3 b  = ld3(verts + 3 * tv.y);
                    F3 c  = ld3(verts + 3 * tv.z);
                    F3 dd = ld3(verts + 3 * tv.w);
                    ce1 = sub3(b, ca);
                    ce2 = sub3(c, ca);
                    ce3 = sub3(dd, ca);
                    cc23 = cross3(ce2, ce3);
                    float det = dot3(ce1, cc23);
                    cinv = 1.0f / det;
                    moved_last = true;
                } else { alive = false; break; }
            }
            if (alive && !ins && moved_last) {
                F3 r = sub3(pw, ca);
                v1 = dot3(r, cc23) * cinv;
                F3 cr3 = cross3(r, ce3);
                v2 = dot3(ce1, cr3) * cinv;
                F3 c2r = cross3(ce2, r);
                v3 = dot3(ce1, c2r) * cinv;
                v0 = 1.0f - (v1 + v2 + v3);
                ins = (v0 >= -1e-6f) && (v1 >= -1e-6f) &&
                      (v2 >= -1e-6f) && (v3 >= -1e-6f);
            }
            bool valid = alive && ins;

            if (lane == 0) {
                int idx = ray * MAXS + k;
                if (valid) {
                    o_ray[idx] = (float)ray;
                    o_tet[idx] = (float)tet;
                    ((float4*)o_bar)[idx] = make_float4(v0, v1, v2, v3);
                    o_pos[3 * idx + 0] = pw.x;
                    o_pos[3 * idx + 1] = pw.y;
                    o_pos[3 * idx + 2] = pw.z;
                } else {
                    o_ray[idx] = -1.0f;
                    o_tet[idx] = -1.0f;
                    ((float4*)o_bar)[idx] = make_float4(0.f, 0.f, 0.f, 0.f);
                    o_pos[3 * idx + 0] = 0.0f;
                    o_pos[3 * idx + 1] = 0.0f;
                    o_pos[3 * idx + 2] = 0.0f;
                }
            }
            k += 1;
        }
    }
}

// ---------------- launch ------------------------------------------------------
extern "C" void kernel_launch(void* const* d_in, const int* in_sizes, int n_in,
                              void* d_out, int out_size) {
    const float* cage   = (const float*)d_in[0];  // (1, 729, 3) f32
    const float* ro     = (const float*)d_in[1];  // (1, 4096, 3) f32
    const float* rd     = (const float*)d_in[2];  // (1, 4096, 3) f32
    const int*   tetras = (const int*)d_in[3];    // (3072, 4) i32
    const int*   faces  = (const int*)d_in[4];    // (3072, 4, 3) i32
    const int*   topo   = (const int*)d_in[5];    // (3072, 4) i32
    float* out = (float*)d_out;

    k_all<<<NRAYS / 32, 1024>>>(cage, ro, rd, tetras, faces, topo, out);
}